// round 7
// baseline (speedup 1.0000x reference)
#include <cuda_runtime.h>
#include <cuda_bf16.h>
#include <cstdint>

// ---------------- problem constants ----------------
#define H_IN   132
#define W_IN   132
#define C_IN   256
#define N_B    2
#define NP     16384
#define KKN    9
#define GRP    4
#define CG     64
#define KDIM   2304
#define M_OFF  72
#define M_PAD  80
#define M_OUT  256
#define BK     32
#define NT     (KDIM / BK)       // 72 k-tiles

typedef unsigned long long ULL;

// ---------------- scratch (device globals) ----------------
__device__ __nv_bfloat16 g_S_hi[(size_t)N_B * KDIM * NP];
__device__ __nv_bfloat16 g_S_lo[(size_t)N_B * KDIM * NP];
__device__ __nv_bfloat16 g_A_hi[(size_t)M_OUT * KDIM];
__device__ __nv_bfloat16 g_A_lo[(size_t)M_OUT * KDIM];
__device__ __nv_bfloat16 g_A1_hi[(size_t)M_PAD * KDIM];
__device__ __nv_bfloat16 g_A1_lo[(size_t)M_PAD * KDIM];
#define XPLANE ((size_t)N_B * C_IN * H_IN * 128)
__device__ __nv_bfloat16 g_X_hi[3 * XPLANE];
__device__ __nv_bfloat16 g_X_lo[3 * XPLANE];
__device__ float g_off[(size_t)N_B * M_OFF * NP];

// ---------------- helpers ----------------
__device__ __forceinline__ uint32_t smem_u32(const void* p) {
    uint32_t a;
    asm("{ .reg .u64 t; cvta.to.shared.u64 t, %1; cvt.u32.u64 %0, t; }" : "=r"(a) : "l"(p));
    return a;
}
__device__ __forceinline__ void cp16(uint32_t dst, const void* src) {
    ULL g;
    asm("cvta.to.global.u64 %0, %1;" : "=l"(g) : "l"(src));
    asm volatile("cp.async.cg.shared.global [%0], [%1], 16;" :: "r"(dst), "l"(g) : "memory");
}
#define CP_COMMIT() asm volatile("cp.async.commit_group;" ::: "memory")
#define CP_WAIT(n)  asm volatile("cp.async.wait_group %0;" :: "n"(n) : "memory")

__device__ __forceinline__ void ldsm_x4(uint32_t* r, uint32_t addr) {
    asm volatile("ldmatrix.sync.aligned.m8n8.x4.shared.b16 {%0,%1,%2,%3}, [%4];"
                 : "=r"(r[0]), "=r"(r[1]), "=r"(r[2]), "=r"(r[3]) : "r"(addr));
}
__device__ __forceinline__ void ldsm_x4t(uint32_t* r, uint32_t addr) {
    asm volatile("ldmatrix.sync.aligned.m8n8.x4.trans.shared.b16 {%0,%1,%2,%3}, [%4];"
                 : "=r"(r[0]), "=r"(r[1]), "=r"(r[2]), "=r"(r[3]) : "r"(addr));
}
__device__ __forceinline__ void mma_bf16(float* c, const uint32_t* a, const uint32_t* b) {
    asm volatile(
        "mma.sync.aligned.m16n8k16.row.col.f32.bf16.bf16.f32 "
        "{%0,%1,%2,%3}, {%4,%5,%6,%7}, {%8,%9}, {%0,%1,%2,%3};"
        : "+f"(c[0]), "+f"(c[1]), "+f"(c[2]), "+f"(c[3])
        : "r"(a[0]), "r"(a[1]), "r"(a[2]), "r"(a[3]), "r"(b[0]), "r"(b[1]));
}

// ================= prep kernels =================
__global__ void prep_w(const float* __restrict__ dw) {
    int idx = blockIdx.x * 256 + threadIdx.x;
    if (idx >= M_OUT * KDIM) return;
    int m = idx / KDIM, j = idx - m * KDIM;
    int g = j / (KKN * CG);
    int r = j - g * (KKN * CG);
    int k = r / CG;
    int c = r - k * CG;
    float v = dw[((size_t)m * C_IN + g * CG + c) * KKN + k];
    __nv_bfloat16 h = __float2bfloat16(v);
    g_A_hi[idx] = h;
    g_A_lo[idx] = __float2bfloat16(v - __bfloat162float(h));
}
__global__ void prep_w1(const float* __restrict__ offw) {
    int idx = blockIdx.x * 256 + threadIdx.x;
    if (idx >= M_PAD * KDIM) return;
    int m = idx / KDIM, j = idx - m * KDIM;
    float v = (m < M_OFF) ? offw[(size_t)m * KDIM + j] : 0.f;
    __nv_bfloat16 h = __float2bfloat16(v);
    g_A1_hi[idx] = h;
    g_A1_lo[idx] = __float2bfloat16(v - __bfloat162float(h));
}
__global__ void prep_x(const float* __restrict__ x) {
    size_t idx = (size_t)blockIdx.x * 256 + threadIdx.x;
    if (idx >= XPLANE) return;
    int wo = (int)(idx & 127);
    size_t rest = idx >> 7;
    int y = (int)(rest % H_IN);
    size_t nc = rest / H_IN;
    const float* row = x + (nc * H_IN + y) * W_IN;
    #pragma unroll
    for (int kx = 0; kx < 3; ++kx) {
        float v = row[wo + 2 * kx];
        __nv_bfloat16 h = __float2bfloat16(v);
        g_X_hi[kx * XPLANE + idx] = h;
        g_X_lo[kx * XPLANE + idx] = __float2bfloat16(v - __bfloat162float(h));
    }
}

// ================= GEMM1: offsets via HMMA, 3-stage cp.async im2col =================
#define A1_PITCH 80
#define B1_PITCH 528
#define SA1 (M_PAD * A1_PITCH)
#define SB1 (BK * B1_PITCH)
#define OFF_A1H 0
#define OFF_A1L SA1
#define OFF_B1H (2 * SA1)
#define OFF_B1L (2 * SA1 + SB1)
#define BUF1 (2 * SA1 + 2 * SB1)         // 46592
#define SMEM1 (3 * BUF1)                 // 139776

__global__ void __launch_bounds__(256, 1)
gemm1_mma(const float* __restrict__ bias)
{
    extern __shared__ char smem[];
    const uint32_t sb = smem_u32(smem);

    const int tid = threadIdx.x;
    const int l   = tid & 31;
    const int wid = tid >> 5;
    const int n   = blockIdx.z;
    const int p0  = blockIdx.x * 256;
    const int ho0 = p0 >> 7;
    const int wn  = wid * 32;

    const int a_row = ((l >> 3) & 1) * 8 + (l & 7);
    const int a_kb  = (l >> 4) * 8;
    const int b_kr  = ((l >> 3) & 1) * 8 + (l & 7);
    const int b_nb  = (l >> 4) * 8;

    float acc[5][4][4];
    #pragma unroll
    for (int i = 0; i < 5; ++i)
        #pragma unroll
        for (int j = 0; j < 4; ++j)
            #pragma unroll
            for (int q = 0; q < 4; ++q) acc[i][j][q] = 0.f;

    auto load_tile = [&](int kt, int b) {
        uint32_t base = sb + b * BUF1;
        #pragma unroll
        for (int i = 0; i < 2; ++i) {
            int c = tid + i * 256;
            if (c < 320) {
                int r = c >> 2, j = c & 3;
                uint32_t dst = base + r * A1_PITCH + j * 16;
                cp16(dst + OFF_A1H, g_A1_hi + (size_t)r * KDIM + kt + j * 8);
                cp16(dst + OFF_A1L, g_A1_lo + (size_t)r * KDIM + kt + j * 8);
            }
        }
        #pragma unroll
        for (int i = 0; i < 4; ++i) {
            int c  = tid + i * 256;
            int r  = c >> 5;
            int ch = c & 31;
            int j  = kt + r;
            int ci = j / 9;
            int kk = j - ci * 9;
            int ky = kk / 3;
            int kx = kk - ky * 3;
            int y  = ho0 + (ch >> 4) + 2 * ky;
            size_t src = (size_t)kx * XPLANE
                       + (((size_t)n * C_IN + ci) * H_IN + y) * 128 + (ch & 15) * 8;
            uint32_t dst = base + r * B1_PITCH + ch * 16;
            cp16(dst + OFF_B1H, g_X_hi + src);
            cp16(dst + OFF_B1L, g_X_lo + src);
        }
        CP_COMMIT();
    };

    load_tile(0, 0);
    load_tile(BK, 1);

    for (int t = 0; t < NT; ++t) {
        int buf = t % 3;
        if (t + 2 < NT) load_tile((t + 2) * BK, (t + 2) % 3);
        else CP_COMMIT();
        CP_WAIT(2);
        __syncthreads();

        uint32_t base = sb + buf * BUF1;
        #pragma unroll
        for (int k16 = 0; k16 < BK; k16 += 16) {
            uint32_t ah[5][4], bh[4][2];
            #pragma unroll
            for (int mt = 0; mt < 5; ++mt)
                ldsm_x4(ah[mt], base + OFF_A1H + (mt * 16 + a_row) * A1_PITCH
                                + (k16 + a_kb) * 2);
            #pragma unroll
            for (int nt2 = 0; nt2 < 2; ++nt2) {
                uint32_t r[4];
                ldsm_x4t(r, base + OFF_B1H + (k16 + b_kr) * B1_PITCH
                            + (wn + nt2 * 16 + b_nb) * 2);
                bh[nt2*2][0] = r[0]; bh[nt2*2][1] = r[1];
                bh[nt2*2+1][0] = r[2]; bh[nt2*2+1][1] = r[3];
            }
            #pragma unroll
            for (int mt = 0; mt < 5; ++mt)
                #pragma unroll
                for (int nt = 0; nt < 4; ++nt)
                    mma_bf16(acc[mt][nt], ah[mt], bh[nt]);
            // stream al against bh
            #pragma unroll
            for (int mt = 0; mt < 5; ++mt) {
                uint32_t al[4];
                ldsm_x4(al, base + OFF_A1L + (mt * 16 + a_row) * A1_PITCH
                            + (k16 + a_kb) * 2);
                #pragma unroll
                for (int nt = 0; nt < 4; ++nt)
                    mma_bf16(acc[mt][nt], al, bh[nt]);
            }
            // stream bl against ah
            #pragma unroll
            for (int nt2 = 0; nt2 < 2; ++nt2) {
                uint32_t r[4];
                ldsm_x4t(r, base + OFF_B1L + (k16 + b_kr) * B1_PITCH
                            + (wn + nt2 * 16 + b_nb) * 2);
                uint32_t b0[2] = {r[0], r[1]};
                uint32_t b1[2] = {r[2], r[3]};
                #pragma unroll
                for (int mt = 0; mt < 5; ++mt) {
                    mma_bf16(acc[mt][nt2*2],   ah[mt], b0);
                    mma_bf16(acc[mt][nt2*2+1], ah[mt], b1);
                }
            }
        }
        __syncthreads();
    }

    float* ob = g_off + (size_t)n * M_OFF * NP + p0 + wn;
    #pragma unroll
    for (int mt = 0; mt < 5; ++mt) {
        int row = mt * 16 + (l >> 2);
        float bv0 = bias[row];
        #pragma unroll
        for (int nt = 0; nt < 4; ++nt) {
            int col = nt * 8 + (l & 3) * 2;
            float* p = ob + (size_t)row * NP + col;
            *reinterpret_cast<float2*>(p) =
                make_float2(acc[mt][nt][0] + bv0, acc[mt][nt][1] + bv0);
        }
        if (mt < 4) {
            float bv1 = bias[row + 8];
            #pragma unroll
            for (int nt = 0; nt < 4; ++nt) {
                int col = nt * 8 + (l & 3) * 2;
                float* p = ob + (size_t)(row + 8) * NP + col;
                *reinterpret_cast<float2*>(p) =
                    make_float2(acc[mt][nt][2] + bv1, acc[mt][nt][3] + bv1);
            }
        }
    }
}

// ================= gather: bilinear sample, 4 pixels/thread =================
__global__ void gather_sampled(const float* __restrict__ x) {
    int n  = blockIdx.z;
    int gk = blockIdx.y;
    int g  = gk / KKN, k = gk % KKN;
    int p  = (blockIdx.x * blockDim.x + threadIdx.x) * 4;
    int ho = p >> 7;
    int ky = k / 3, kx = k % 3;

    const float* offbase = g_off + ((size_t)n * M_OFF + g * 18 + k * 2) * NP + p;
    float4 dy = *reinterpret_cast<const float4*>(offbase);
    float4 dx = *reinterpret_cast<const float4*>(offbase + NP);
    float dys[4] = {dy.x, dy.y, dy.z, dy.w};
    float dxs[4] = {dx.x, dx.y, dx.z, dx.w};

    float w00[4], w01[4], w10[4], w11[4];
    int i00[4], i01[4], i10[4], i11[4];
    #pragma unroll
    for (int s = 0; s < 4; ++s) {
        int wo = (p + s) & 127;
        float yf = dys[s] + (float)(ky * 2 + ho);
        float xf = dxs[s] + (float)(kx * 2 + wo);
        float y0f = floorf(yf), x0f = floorf(xf);
        float ly = yf - y0f, lx = xf - x0f;
        int y0 = (int)y0f, x0 = (int)x0f;
        int y1 = y0 + 1,  x1 = x0 + 1;

        float a = (1.f - ly) * (1.f - lx);
        float b = (1.f - ly) * lx;
        float c = ly * (1.f - lx);
        float d = ly * lx;

        bool vy0 = (y0 >= 0) & (y0 < H_IN);
        bool vy1 = (y1 >= 0) & (y1 < H_IN);
        bool vx0 = (x0 >= 0) & (x0 < W_IN);
        bool vx1 = (x1 >= 0) & (x1 < W_IN);
        w00[s] = a * (float)(vy0 & vx0);
        w01[s] = b * (float)(vy0 & vx1);
        w10[s] = c * (float)(vy1 & vx0);
        w11[s] = d * (float)(vy1 & vx1);

        int cy0 = min(max(y0, 0), H_IN - 1);
        int cy1 = min(max(y1, 0), H_IN - 1);
        int cx0 = min(max(x0, 0), W_IN - 1);
        int cx1 = min(max(x1, 0), W_IN - 1);
        i00[s] = cy0 * W_IN + cx0;
        i01[s] = cy0 * W_IN + cx1;
        i10[s] = cy1 * W_IN + cx0;
        i11[s] = cy1 * W_IN + cx1;
    }

    const float* xb = x + ((size_t)n * C_IN + g * CG) * (H_IN * W_IN);
    size_t base = ((size_t)n * KDIM + (size_t)(g * KKN + k) * CG) * NP + p;
    __nv_bfloat16* hib = g_S_hi + base;
    __nv_bfloat16* lob = g_S_lo + base;

    #pragma unroll 2
    for (int c = 0; c < CG; ++c) {
        const float* xc = xb + c * (H_IN * W_IN);
        float v[4];
        #pragma unroll
        for (int s = 0; s < 4; ++s)
            v[s] = w00[s] * __ldg(xc + i00[s]) + w01[s] * __ldg(xc + i01[s])
                 + w10[s] * __ldg(xc + i10[s]) + w11[s] * __ldg(xc + i11[s]);
        __nv_bfloat162 h0 = __floats2bfloat162_rn(v[0], v[1]);
        __nv_bfloat162 h1 = __floats2bfloat162_rn(v[2], v[3]);
        __nv_bfloat162 l0 = __floats2bfloat162_rn(v[0] - __bfloat162float(h0.x),
                                                  v[1] - __bfloat162float(h0.y));
        __nv_bfloat162 l1 = __floats2bfloat162_rn(v[2] - __bfloat162float(h1.x),
                                                  v[3] - __bfloat162float(h1.y));
        uint2 hp = make_uint2(*reinterpret_cast<uint32_t*>(&h0),
                              *reinterpret_cast<uint32_t*>(&h1));
        uint2 lp = make_uint2(*reinterpret_cast<uint32_t*>(&l0),
                              *reinterpret_cast<uint32_t*>(&l1));
        *reinterpret_cast<uint2*>(hib + (size_t)c * NP) = hp;
        *reinterpret_cast<uint2*>(lob + (size_t)c * NP) = lp;
    }
}

// ================= GEMM2: HMMA bf16, 3-term split, 3-stage pipeline =================
#define A_PITCH 80
#define B_PITCH 272
#define SA_PLANE (128 * A_PITCH)
#define SB_PLANE (32 * B_PITCH)
#define OFF_AH 0
#define OFF_AL SA_PLANE
#define OFF_BH (2 * SA_PLANE)
#define OFF_BL (2 * SA_PLANE + SB_PLANE)
#define BUF_BYTES (2 * SA_PLANE + 2 * SB_PLANE)   // 37888
#define SMEM2_BYTES (3 * BUF_BYTES)               // 113664

__global__ void __launch_bounds__(256, 2)
gemm2_mma(float* __restrict__ out)
{
    extern __shared__ char smem[];
    const uint32_t sb = smem_u32(smem);

    const int tid = threadIdx.x;
    const int wid = tid >> 5;
    const int l   = tid & 31;

    const int my = blockIdx.x;
    const int bx = blockIdx.y;
    const int n  = blockIdx.z;

    const int wm = (wid & 1) * 64;
    const int wn = (wid >> 1) * 32;

    const __nv_bfloat16* Ah = g_A_hi + (size_t)my * 128 * KDIM;
    const __nv_bfloat16* Al = g_A_lo + (size_t)my * 128 * KDIM;
    const __nv_bfloat16* Sh = g_S_hi + (size_t)n * KDIM * NP + (size_t)bx * 128;
    const __nv_bfloat16* Sl = g_S_lo + (size_t)n * KDIM * NP + (size_t)bx * 128;

    const int a_row = ((l >> 3) & 1) * 8 + (l & 7);
    const int a_kb  = (l >> 4) * 8;
    const int b_kr  = ((l >> 3) & 1) * 8 + (l & 7);
    const int b_nb  = (l >> 4) * 8;

    float acc[4][4][4];
    #pragma unroll
    for (int i = 0; i < 4; ++i)
        #pragma unroll
        for (int j = 0; j < 4; ++j)
            #pragma unroll
            for (int q = 0; q < 4; ++q) acc[i][j][q] = 0.f;

    auto load_tile = [&](int kt, int b) {
        uint32_t base = sb + b * BUF_BYTES;
        #pragma unroll
        for (int i = 0; i < 2; ++i) {
            int c = tid + i * 256;
            int r = c >> 2, j = c & 3;
            uint32_t dst = base + r * A_PITCH + j * 16;
            cp16(dst + OFF_AH, Ah + (size_t)r * KDIM + kt + j * 8);
            cp16(dst + OFF_AL, Al + (size_t)r * KDIM + kt + j * 8);
        }
        #pragma unroll
        for (int i = 0; i < 2; ++i) {
            int c = tid + i * 256;
            int r = c >> 4, j = c & 15;
            uint32_t dst = base + r * B_PITCH + j * 16;
            cp16(dst + OFF_BH, Sh + (size_t)(kt + r) * NP + j * 8);
            cp16(dst + OFF_BL, Sl + (size_t)(kt + r) * NP + j * 8);
        }
        CP_COMMIT();
    };

    load_tile(0, 0);
    load_tile(BK, 1);

    for (int t = 0; t < NT; ++t) {
        int buf = t % 3;
        if (t + 2 < NT) load_tile((t + 2) * BK, (t + 2) % 3);
        else CP_COMMIT();
        CP_WAIT(2);
        __syncthreads();

        uint32_t base = sb + buf * BUF_BYTES;
        #pragma unroll
        for (int k16 = 0; k16 < BK; k16 += 16) {
            uint32_t ah[4][4], bh[4][2];
            #pragma unroll
            for (int mt = 0; mt < 4; ++mt)
                ldsm_x4(ah[mt], base + OFF_AH + (wm + mt * 16 + a_row) * A_PITCH
                                + (k16 + a_kb) * 2);
            #pragma unroll
            for (int nt2 = 0; nt2 < 2; ++nt2) {
                uint32_t r[4];
                ldsm_x4t(r, base + OFF_BH + (k16 + b_kr) * B_PITCH
                            + (wn + nt2 * 16 + b_nb) * 2);
                bh[nt2*2][0] = r[0]; bh[nt2*2][1] = r[1];
                bh[nt2*2+1][0] = r[2]; bh[nt2*2+1][1] = r[3];
            }
            #pragma unroll
            for (int mt = 0; mt < 4; ++mt)
                #pragma unroll
                for (int nt = 0; nt < 4; ++nt)
                    mma_bf16(acc[mt][nt], ah[mt], bh[nt]);
            // stream al against bh
            #pragma unroll
            for (int mt = 0; mt < 4; ++mt) {
                uint32_t al[4];
                ldsm_x4(al, base + OFF_AL + (wm + mt * 16 + a_row) * A_PITCH
                            + (k16 + a_kb) * 2);
                #pragma unroll
                for (int nt = 0; nt < 4; ++nt)
                    mma_bf16(acc[mt][nt], al, bh[nt]);
            }
            // stream bl against ah
            #pragma unroll
            for (int nt2 = 0; nt2 < 2; ++nt2) {
                uint32_t r[4];
                ldsm_x4t(r, base + OFF_BL + (k16 + b_kr) * B_PITCH
                            + (wn + nt2 * 16 + b_nb) * 2);
                uint32_t b0[2] = {r[0], r[1]};
                uint32_t b1[2] = {r[2], r[3]};
                #pragma unroll
                for (int mt = 0; mt < 4; ++mt) {
                    mma_bf16(acc[mt][nt2*2],   ah[mt], b0);
                    mma_bf16(acc[mt][nt2*2+1], ah[mt], b1);
                }
            }
        }
        __syncthreads();
    }

    float* ob = out + ((size_t)n * M_OUT + my * 128 + wm) * NP + (size_t)bx * 128 + wn;
    #pragma unroll
    for (int mt = 0; mt < 4; ++mt) {
        #pragma unroll
        for (int nt = 0; nt < 4; ++nt) {
            int row = mt * 16 + (l >> 2);
            int col = nt * 8 + (l & 3) * 2;
            float* p0 = ob + (size_t)row * NP + col;
            *reinterpret_cast<float2*>(p0) =
                make_float2(acc[mt][nt][0], acc[mt][nt][1]);
            *reinterpret_cast<float2*>(p0 + 8 * NP) =
                make_float2(acc[mt][nt][2], acc[mt][nt][3]);
        }
    }
}

// ---------------- launch ----------------
extern "C" void kernel_launch(void* const* d_in, const int* in_sizes, int n_in,
                              void* d_out, int out_size) {
    const float* x    = (const float*)d_in[0];
    const float* offw = (const float*)d_in[1];
    const float* offb = (const float*)d_in[2];
    const float* dw   = (const float*)d_in[3];
    float* out = (float*)d_out;

    cudaFuncSetAttribute(gemm1_mma, cudaFuncAttributeMaxDynamicSharedMemorySize, SMEM1);
    cudaFuncSetAttribute(gemm2_mma, cudaFuncAttributeMaxDynamicSharedMemorySize, SMEM2_BYTES);

    prep_w <<<(M_OUT * KDIM + 255) / 256, 256>>>(dw);
    prep_w1<<<(M_PAD * KDIM + 255) / 256, 256>>>(offw);
    prep_x <<<(int)((XPLANE + 255) / 256), 256>>>(x);
    {
        dim3 grid(NP / 256, 1, N_B);
        gemm1_mma<<<grid, 256, SMEM1>>>(offb);
    }
    {
        dim3 grid(NP / 1024, GRP * KKN, N_B);
        gather_sampled<<<grid, 256>>>(x);
    }
    {
        dim3 grid(2, NP / 128, N_B);
        gemm2_mma<<<grid, 256, SMEM2_BYTES>>>(out);
    }
}

// round 8
// speedup vs baseline: 1.0171x; 1.0171x over previous
#include <cuda_runtime.h>
#include <cuda_bf16.h>
#include <cstdint>

// ---------------- problem constants ----------------
#define H_IN   132
#define W_IN   132
#define C_IN   256
#define N_B    2
#define NP     16384
#define KKN    9
#define GRP    4
#define CG     64
#define KDIM   2304
#define M_OFF  72
#define M_PAD  80
#define M_OUT  256
#define BK     32
#define NT     (KDIM / BK)       // 72 k-tiles

typedef unsigned long long ULL;

// ---------------- scratch (device globals) ----------------
__device__ __nv_bfloat16 g_S_hi[(size_t)N_B * KDIM * NP];
__device__ __nv_bfloat16 g_S_lo[(size_t)N_B * KDIM * NP];
__device__ __nv_bfloat16 g_A_hi[(size_t)M_OUT * KDIM];
__device__ __nv_bfloat16 g_A_lo[(size_t)M_OUT * KDIM];
__device__ __nv_bfloat16 g_A1_hi[(size_t)M_PAD * KDIM];
__device__ __nv_bfloat16 g_A1_lo[(size_t)M_PAD * KDIM];
#define XPLANE ((size_t)N_B * C_IN * H_IN * 128)
__device__ __nv_bfloat16 g_X_hi[3 * XPLANE];
__device__ __nv_bfloat16 g_X_lo[3 * XPLANE];
__device__ float g_off[(size_t)N_B * M_OFF * NP];

// ---------------- helpers ----------------
__device__ __forceinline__ uint32_t smem_u32(const void* p) {
    uint32_t a;
    asm("{ .reg .u64 t; cvta.to.shared.u64 t, %1; cvt.u32.u64 %0, t; }" : "=r"(a) : "l"(p));
    return a;
}
__device__ __forceinline__ void cp16(uint32_t dst, const void* src) {
    ULL g;
    asm("cvta.to.global.u64 %0, %1;" : "=l"(g) : "l"(src));
    asm volatile("cp.async.cg.shared.global [%0], [%1], 16;" :: "r"(dst), "l"(g) : "memory");
}
#define CP_COMMIT() asm volatile("cp.async.commit_group;" ::: "memory")
#define CP_WAIT(n)  asm volatile("cp.async.wait_group %0;" :: "n"(n) : "memory")

__device__ __forceinline__ void ldsm_x4(uint32_t* r, uint32_t addr) {
    asm volatile("ldmatrix.sync.aligned.m8n8.x4.shared.b16 {%0,%1,%2,%3}, [%4];"
                 : "=r"(r[0]), "=r"(r[1]), "=r"(r[2]), "=r"(r[3]) : "r"(addr));
}
__device__ __forceinline__ void ldsm_x4t(uint32_t* r, uint32_t addr) {
    asm volatile("ldmatrix.sync.aligned.m8n8.x4.trans.shared.b16 {%0,%1,%2,%3}, [%4];"
                 : "=r"(r[0]), "=r"(r[1]), "=r"(r[2]), "=r"(r[3]) : "r"(addr));
}
__device__ __forceinline__ void mma_bf16(float* c, const uint32_t* a, const uint32_t* b) {
    asm volatile(
        "mma.sync.aligned.m16n8k16.row.col.f32.bf16.bf16.f32 "
        "{%0,%1,%2,%3}, {%4,%5,%6,%7}, {%8,%9}, {%0,%1,%2,%3};"
        : "+f"(c[0]), "+f"(c[1]), "+f"(c[2]), "+f"(c[3])
        : "r"(a[0]), "r"(a[1]), "r"(a[2]), "r"(a[3]), "r"(b[0]), "r"(b[1]));
}

// ================= prep kernels =================
__global__ void prep_w(const float* __restrict__ dw) {
    int idx = blockIdx.x * 256 + threadIdx.x;
    if (idx >= M_OUT * KDIM) return;
    int m = idx / KDIM, j = idx - m * KDIM;
    int g = j / (KKN * CG);
    int r = j - g * (KKN * CG);
    int k = r / CG;
    int c = r - k * CG;
    float v = dw[((size_t)m * C_IN + g * CG + c) * KKN + k];
    __nv_bfloat16 h = __float2bfloat16(v);
    g_A_hi[idx] = h;
    g_A_lo[idx] = __float2bfloat16(v - __bfloat162float(h));
}
__global__ void prep_w1(const float* __restrict__ offw) {
    int idx = blockIdx.x * 256 + threadIdx.x;
    if (idx >= M_PAD * KDIM) return;
    int m = idx / KDIM, j = idx - m * KDIM;
    float v = (m < M_OFF) ? offw[(size_t)m * KDIM + j] : 0.f;
    __nv_bfloat16 h = __float2bfloat16(v);
    g_A1_hi[idx] = h;
    g_A1_lo[idx] = __float2bfloat16(v - __bfloat162float(h));
}
__global__ void prep_x(const float* __restrict__ x) {
    size_t idx = (size_t)blockIdx.x * 256 + threadIdx.x;
    if (idx >= XPLANE) return;
    int wo = (int)(idx & 127);
    size_t rest = idx >> 7;
    int y = (int)(rest % H_IN);
    size_t nc = rest / H_IN;
    const float* row = x + (nc * H_IN + y) * W_IN;
    #pragma unroll
    for (int kx = 0; kx < 3; ++kx) {
        float v = row[wo + 2 * kx];
        __nv_bfloat16 h = __float2bfloat16(v);
        g_X_hi[kx * XPLANE + idx] = h;
        g_X_lo[kx * XPLANE + idx] = __float2bfloat16(v - __bfloat162float(h));
    }
}

// ================= GEMM1: offsets via HMMA (80m x 128n x 32k, 2-stage) =================
// 8 warps, each 80m x 16n. Grid (128, 1, 2) -> 2 CTAs/SM.
#define A1_PITCH 80
#define B1_PITCH 272
#define SA1 (M_PAD * A1_PITCH)           // 6400
#define SB1 (BK * B1_PITCH)              // 8704
#define OFF_A1H 0
#define OFF_A1L SA1
#define OFF_B1H (2 * SA1)
#define OFF_B1L (2 * SA1 + SB1)
#define BUF1 (2 * SA1 + 2 * SB1)         // 30208
#define SMEM1 (2 * BUF1)                 // 60416

__global__ void __launch_bounds__(256, 2)
gemm1_mma(const float* __restrict__ bias)
{
    extern __shared__ char smem[];
    const uint32_t sb = smem_u32(smem);

    const int tid = threadIdx.x;
    const int l   = tid & 31;
    const int wid = tid >> 5;
    const int n   = blockIdx.z;
    const int p0  = blockIdx.x * 128;     // one full output row
    const int ho0 = blockIdx.x;
    const int wn  = wid * 16;             // warp n base

    const int a_row = ((l >> 3) & 1) * 8 + (l & 7);
    const int a_kb  = (l >> 4) * 8;
    const int b_kr  = ((l >> 3) & 1) * 8 + (l & 7);
    const int b_nb  = (l >> 4) * 8;

    float acc[5][2][4];
    #pragma unroll
    for (int i = 0; i < 5; ++i)
        #pragma unroll
        for (int j = 0; j < 2; ++j)
            #pragma unroll
            for (int q = 0; q < 4; ++q) acc[i][j][q] = 0.f;

    auto load_tile = [&](int kt, int b) {
        uint32_t base = sb + b * BUF1;
        // A: 320 16B-chunks per plane
        #pragma unroll
        for (int i = 0; i < 2; ++i) {
            int c = tid + i * 256;
            if (c < 320) {
                int r = c >> 2, j = c & 3;
                uint32_t dst = base + r * A1_PITCH + j * 16;
                cp16(dst + OFF_A1H, g_A1_hi + (size_t)r * KDIM + kt + j * 8);
                cp16(dst + OFF_A1L, g_A1_lo + (size_t)r * KDIM + kt + j * 8);
            }
        }
        // B: 512 16B-chunks per plane (32 k-rows x 16 chunks of this output row)
        #pragma unroll
        for (int i = 0; i < 2; ++i) {
            int c  = tid + i * 256;
            int r  = c >> 4;            // k-row 0..31
            int ch = c & 15;            // 16B chunk (8 px)
            int j  = kt + r;
            int ci = j / 9;
            int kk = j - ci * 9;
            int ky = kk / 3;
            int kx = kk - ky * 3;
            int y  = ho0 + 2 * ky;
            size_t src = (size_t)kx * XPLANE
                       + (((size_t)n * C_IN + ci) * H_IN + y) * 128 + ch * 8;
            uint32_t dst = base + r * B1_PITCH + ch * 16;
            cp16(dst + OFF_B1H, g_X_hi + src);
            cp16(dst + OFF_B1L, g_X_lo + src);
        }
        CP_COMMIT();
    };

    load_tile(0, 0);

    for (int t = 0; t < NT; ++t) {
        int b = t & 1;
        if (t + 1 < NT) {
            load_tile((t + 1) * BK, b ^ 1);
            CP_WAIT(1);
        } else {
            CP_WAIT(0);
        }
        __syncthreads();

        uint32_t base = sb + b * BUF1;
        #pragma unroll
        for (int k16 = 0; k16 < BK; k16 += 16) {
            uint32_t ah[5][4], bh[2][2], bl[2][2];
            #pragma unroll
            for (int mt = 0; mt < 5; ++mt)
                ldsm_x4(ah[mt], base + OFF_A1H + (mt * 16 + a_row) * A1_PITCH
                                + (k16 + a_kb) * 2);
            {
                uint32_t r[4];
                ldsm_x4t(r, base + OFF_B1H + (k16 + b_kr) * B1_PITCH
                            + (wn + b_nb) * 2);
                bh[0][0] = r[0]; bh[0][1] = r[1];
                bh[1][0] = r[2]; bh[1][1] = r[3];
            }
            #pragma unroll
            for (int mt = 0; mt < 5; ++mt)
                #pragma unroll
                for (int nt = 0; nt < 2; ++nt)
                    mma_bf16(acc[mt][nt], ah[mt], bh[nt]);
            {
                uint32_t r[4];
                ldsm_x4t(r, base + OFF_B1L + (k16 + b_kr) * B1_PITCH
                            + (wn + b_nb) * 2);
                bl[0][0] = r[0]; bl[0][1] = r[1];
                bl[1][0] = r[2]; bl[1][1] = r[3];
            }
            #pragma unroll
            for (int mt = 0; mt < 5; ++mt)
                #pragma unroll
                for (int nt = 0; nt < 2; ++nt)
                    mma_bf16(acc[mt][nt], ah[mt], bl[nt]);
            #pragma unroll
            for (int mt = 0; mt < 5; ++mt) {
                uint32_t al[4];
                ldsm_x4(al, base + OFF_A1L + (mt * 16 + a_row) * A1_PITCH
                            + (k16 + a_kb) * 2);
                #pragma unroll
                for (int nt = 0; nt < 2; ++nt)
                    mma_bf16(acc[mt][nt], al, bh[nt]);
            }
        }
        __syncthreads();
    }

    // epilogue: rows 0..71, add bias
    float* ob = g_off + (size_t)n * M_OFF * NP + p0 + wn;
    #pragma unroll
    for (int mt = 0; mt < 5; ++mt) {
        int row = mt * 16 + (l >> 2);
        float bv0 = bias[row];
        #pragma unroll
        for (int nt = 0; nt < 2; ++nt) {
            int col = nt * 8 + (l & 3) * 2;
            float* p = ob + (size_t)row * NP + col;
            *reinterpret_cast<float2*>(p) =
                make_float2(acc[mt][nt][0] + bv0, acc[mt][nt][1] + bv0);
        }
        if (mt < 4) {
            float bv1 = bias[row + 8];
            #pragma unroll
            for (int nt = 0; nt < 2; ++nt) {
                int col = nt * 8 + (l & 3) * 2;
                float* p = ob + (size_t)(row + 8) * NP + col;
                *reinterpret_cast<float2*>(p) =
                    make_float2(acc[mt][nt][2] + bv1, acc[mt][nt][3] + bv1);
            }
        }
    }
}

// ================= gather: bilinear sample, 4 pixels/thread =================
__global__ void gather_sampled(const float* __restrict__ x) {
    int n  = blockIdx.z;
    int gk = blockIdx.y;
    int g  = gk / KKN, k = gk % KKN;
    int p  = (blockIdx.x * blockDim.x + threadIdx.x) * 4;
    int ho = p >> 7;
    int ky = k / 3, kx = k % 3;

    const float* offbase = g_off + ((size_t)n * M_OFF + g * 18 + k * 2) * NP + p;
    float4 dy = *reinterpret_cast<const float4*>(offbase);
    float4 dx = *reinterpret_cast<const float4*>(offbase + NP);
    float dys[4] = {dy.x, dy.y, dy.z, dy.w};
    float dxs[4] = {dx.x, dx.y, dx.z, dx.w};

    float w00[4], w01[4], w10[4], w11[4];
    int i00[4], i01[4], i10[4], i11[4];
    #pragma unroll
    for (int s = 0; s < 4; ++s) {
        int wo = (p + s) & 127;
        float yf = dys[s] + (float)(ky * 2 + ho);
        float xf = dxs[s] + (float)(kx * 2 + wo);
        float y0f = floorf(yf), x0f = floorf(xf);
        float ly = yf - y0f, lx = xf - x0f;
        int y0 = (int)y0f, x0 = (int)x0f;
        int y1 = y0 + 1,  x1 = x0 + 1;

        float a = (1.f - ly) * (1.f - lx);
        float b = (1.f - ly) * lx;
        float c = ly * (1.f - lx);
        float d = ly * lx;

        bool vy0 = (y0 >= 0) & (y0 < H_IN);
        bool vy1 = (y1 >= 0) & (y1 < H_IN);
        bool vx0 = (x0 >= 0) & (x0 < W_IN);
        bool vx1 = (x1 >= 0) & (x1 < W_IN);
        w00[s] = a * (float)(vy0 & vx0);
        w01[s] = b * (float)(vy0 & vx1);
        w10[s] = c * (float)(vy1 & vx0);
        w11[s] = d * (float)(vy1 & vx1);

        int cy0 = min(max(y0, 0), H_IN - 1);
        int cy1 = min(max(y1, 0), H_IN - 1);
        int cx0 = min(max(x0, 0), W_IN - 1);
        int cx1 = min(max(x1, 0), W_IN - 1);
        i00[s] = cy0 * W_IN + cx0;
        i01[s] = cy0 * W_IN + cx1;
        i10[s] = cy1 * W_IN + cx0;
        i11[s] = cy1 * W_IN + cx1;
    }

    const float* xb = x + ((size_t)n * C_IN + g * CG) * (H_IN * W_IN);
    size_t base = ((size_t)n * KDIM + (size_t)(g * KKN + k) * CG) * NP + p;
    __nv_bfloat16* hib = g_S_hi + base;
    __nv_bfloat16* lob = g_S_lo + base;

    #pragma unroll 2
    for (int c = 0; c < CG; ++c) {
        const float* xc = xb + c * (H_IN * W_IN);
        float v[4];
        #pragma unroll
        for (int s = 0; s < 4; ++s)
            v[s] = w00[s] * __ldg(xc + i00[s]) + w01[s] * __ldg(xc + i01[s])
                 + w10[s] * __ldg(xc + i10[s]) + w11[s] * __ldg(xc + i11[s]);
        __nv_bfloat162 h0 = __floats2bfloat162_rn(v[0], v[1]);
        __nv_bfloat162 h1 = __floats2bfloat162_rn(v[2], v[3]);
        __nv_bfloat162 l0 = __floats2bfloat162_rn(v[0] - __bfloat162float(h0.x),
                                                  v[1] - __bfloat162float(h0.y));
        __nv_bfloat162 l1 = __floats2bfloat162_rn(v[2] - __bfloat162float(h1.x),
                                                  v[3] - __bfloat162float(h1.y));
        uint2 hp = make_uint2(*reinterpret_cast<uint32_t*>(&h0),
                              *reinterpret_cast<uint32_t*>(&h1));
        uint2 lp = make_uint2(*reinterpret_cast<uint32_t*>(&l0),
                              *reinterpret_cast<uint32_t*>(&l1));
        *reinterpret_cast<uint2*>(hib + (size_t)c * NP) = hp;
        *reinterpret_cast<uint2*>(lob + (size_t)c * NP) = lp;
    }
}

// ================= GEMM2: HMMA bf16, 3-term split, 2-stage (round-6 config) =================
#define A_PITCH 80
#define B_PITCH 272
#define SA_PLANE (128 * A_PITCH)
#define SB_PLANE (32 * B_PITCH)
#define OFF_AH 0
#define OFF_AL SA_PLANE
#define OFF_BH (2 * SA_PLANE)
#define OFF_BL (2 * SA_PLANE + SB_PLANE)
#define BUF_BYTES (2 * SA_PLANE + 2 * SB_PLANE)   // 37888
#define SMEM2_BYTES (2 * BUF_BYTES)               // 75776

__global__ void __launch_bounds__(256, 2)
gemm2_mma(float* __restrict__ out)
{
    extern __shared__ char smem[];
    const uint32_t sb = smem_u32(smem);

    const int tid = threadIdx.x;
    const int wid = tid >> 5;
    const int l   = tid & 31;

    const int my = blockIdx.x;
    const int bx = blockIdx.y;
    const int n  = blockIdx.z;

    const int wm = (wid & 1) * 64;
    const int wn = (wid >> 1) * 32;

    const __nv_bfloat16* Ah = g_A_hi + (size_t)my * 128 * KDIM;
    const __nv_bfloat16* Al = g_A_lo + (size_t)my * 128 * KDIM;
    const __nv_bfloat16* Sh = g_S_hi + (size_t)n * KDIM * NP + (size_t)bx * 128;
    const __nv_bfloat16* Sl = g_S_lo + (size_t)n * KDIM * NP + (size_t)bx * 128;

    const int a_row = ((l >> 3) & 1) * 8 + (l & 7);
    const int a_kb  = (l >> 4) * 8;
    const int b_kr  = ((l >> 3) & 1) * 8 + (l & 7);
    const int b_nb  = (l >> 4) * 8;

    float acc[4][4][4];
    #pragma unroll
    for (int i = 0; i < 4; ++i)
        #pragma unroll
        for (int j = 0; j < 4; ++j)
            #pragma unroll
            for (int q = 0; q < 4; ++q) acc[i][j][q] = 0.f;

    auto load_tile = [&](int kt, int b) {
        uint32_t base = sb + b * BUF_BYTES;
        #pragma unroll
        for (int i = 0; i < 2; ++i) {
            int c = tid + i * 256;
            int r = c >> 2, j = c & 3;
            uint32_t dst = base + r * A_PITCH + j * 16;
            cp16(dst + OFF_AH, Ah + (size_t)r * KDIM + kt + j * 8);
            cp16(dst + OFF_AL, Al + (size_t)r * KDIM + kt + j * 8);
        }
        #pragma unroll
        for (int i = 0; i < 2; ++i) {
            int c = tid + i * 256;
            int r = c >> 4, j = c & 15;
            uint32_t dst = base + r * B_PITCH + j * 16;
            cp16(dst + OFF_BH, Sh + (size_t)(kt + r) * NP + j * 8);
            cp16(dst + OFF_BL, Sl + (size_t)(kt + r) * NP + j * 8);
        }
        CP_COMMIT();
    };

    load_tile(0, 0);

    for (int t = 0; t < NT; ++t) {
        int b = t & 1;
        if (t + 1 < NT) {
            load_tile((t + 1) * BK, b ^ 1);
            CP_WAIT(1);
        } else {
            CP_WAIT(0);
        }
        __syncthreads();

        uint32_t base = sb + b * BUF_BYTES;
        #pragma unroll
        for (int k16 = 0; k16 < BK; k16 += 16) {
            uint32_t ah[4][4], bh[4][2], bl[4][2];
            #pragma unroll
            for (int mt = 0; mt < 4; ++mt)
                ldsm_x4(ah[mt], base + OFF_AH + (wm + mt * 16 + a_row) * A_PITCH
                                + (k16 + a_kb) * 2);
            #pragma unroll
            for (int nt2 = 0; nt2 < 2; ++nt2) {
                uint32_t r[4];
                ldsm_x4t(r, base + OFF_BH + (k16 + b_kr) * B_PITCH
                            + (wn + nt2 * 16 + b_nb) * 2);
                bh[nt2*2][0] = r[0]; bh[nt2*2][1] = r[1];
                bh[nt2*2+1][0] = r[2]; bh[nt2*2+1][1] = r[3];
            }
            #pragma unroll
            for (int mt = 0; mt < 4; ++mt)
                #pragma unroll
                for (int nt = 0; nt < 4; ++nt)
                    mma_bf16(acc[mt][nt], ah[mt], bh[nt]);
            #pragma unroll
            for (int nt2 = 0; nt2 < 2; ++nt2) {
                uint32_t r[4];
                ldsm_x4t(r, base + OFF_BL + (k16 + b_kr) * B_PITCH
                            + (wn + nt2 * 16 + b_nb) * 2);
                bl[nt2*2][0] = r[0]; bl[nt2*2][1] = r[1];
                bl[nt2*2+1][0] = r[2]; bl[nt2*2+1][1] = r[3];
            }
            #pragma unroll
            for (int mt = 0; mt < 4; ++mt)
                #pragma unroll
                for (int nt = 0; nt < 4; ++nt)
                    mma_bf16(acc[mt][nt], ah[mt], bl[nt]);
            #pragma unroll
            for (int mt = 0; mt < 4; ++mt) {
                uint32_t al[4];
                ldsm_x4(al, base + OFF_AL + (wm + mt * 16 + a_row) * A_PITCH
                            + (k16 + a_kb) * 2);
                #pragma unroll
                for (int nt = 0; nt < 4; ++nt)
                    mma_bf16(acc[mt][nt], al, bh[nt]);
            }
        }
        __syncthreads();
    }

    float* ob = out + ((size_t)n * M_OUT + my * 128 + wm) * NP + (size_t)bx * 128 + wn;
    #pragma unroll
    for (int mt = 0; mt < 4; ++mt) {
        #pragma unroll
        for (int nt = 0; nt < 4; ++nt) {
            int row = mt * 16 + (l >> 2);
            int col = nt * 8 + (l & 3) * 2;
            float* p0 = ob + (size_t)row * NP + col;
            *reinterpret_cast<float2*>(p0) =
                make_float2(acc[mt][nt][0], acc[mt][nt][1]);
            *reinterpret_cast<float2*>(p0 + 8 * NP) =
                make_float2(acc[mt][nt][2], acc[mt][nt][3]);
        }
    }
}

// ---------------- launch ----------------
extern "C" void kernel_launch(void* const* d_in, const int* in_sizes, int n_in,
                              void* d_out, int out_size) {
    const float* x    = (const float*)d_in[0];
    const float* offw = (const float*)d_in[1];
    const float* offb = (const float*)d_in[2];
    const float* dw   = (const float*)d_in[3];
    float* out = (float*)d_out;

    cudaFuncSetAttribute(gemm1_mma, cudaFuncAttributeMaxDynamicSharedMemorySize, SMEM1);
    cudaFuncSetAttribute(gemm2_mma, cudaFuncAttributeMaxDynamicSharedMemorySize, SMEM2_BYTES);

    prep_w <<<(M_OUT * KDIM + 255) / 256, 256>>>(dw);
    prep_w1<<<(M_PAD * KDIM + 255) / 256, 256>>>(offw);
    prep_x <<<(int)((XPLANE + 255) / 256), 256>>>(x);
    // 1) offsets via tensor cores (80x128 tiles, 2 CTAs/SM)
    {
        dim3 grid(NP / 128, 1, N_B);
        gemm1_mma<<<grid, 256, SMEM1>>>(offb);
    }
    // 2) bilinear sampled matrix -> bf16 hi/lo planes (4 px/thread)
    {
        dim3 grid(NP / 1024, GRP * KKN, N_B);
        gather_sampled<<<grid, 256>>>(x);
    }
    // 3) out = dw @ sampled
    {
        dim3 grid(2, NP / 128, N_B);
        gemm2_mma<<<grid, 256, SMEM2_BYTES>>>(out);
    }
}

// round 9
// speedup vs baseline: 1.0811x; 1.0630x over previous
#include <cuda_runtime.h>
#include <cuda_bf16.h>
#include <cstdint>

// ---------------- problem constants ----------------
#define H_IN   132
#define W_IN   132
#define C_IN   256
#define N_B    2
#define NP     16384
#define KKN    9
#define GRP    4
#define CG     64
#define KDIM   2304
#define M_OFF  72
#define M_PAD  80
#define M_OUT  256
#define BK     32
#define NT     (KDIM / BK)       // 72 k-tiles

typedef unsigned long long ULL;

// ---------------- scratch (device globals) ----------------
__device__ __nv_bfloat16 g_S_hi[(size_t)N_B * KDIM * NP];
__device__ __nv_bfloat16 g_S_lo[(size_t)N_B * KDIM * NP];
__device__ __nv_bfloat16 g_A_hi[(size_t)M_OUT * KDIM];
__device__ __nv_bfloat16 g_A_lo[(size_t)M_OUT * KDIM];
__device__ __nv_bfloat16 g_A1_hi[(size_t)M_PAD * KDIM];
__device__ __nv_bfloat16 g_A1_lo[(size_t)M_PAD * KDIM];
#define XPLANE ((size_t)N_B * C_IN * H_IN * 128)
__device__ __nv_bfloat16 g_X_hi[3 * XPLANE];
__device__ __nv_bfloat16 g_X_lo[3 * XPLANE];
__device__ float g_off[(size_t)N_B * M_OFF * NP];

// ---------------- helpers ----------------
__device__ __forceinline__ uint32_t smem_u32(const void* p) {
    uint32_t a;
    asm("{ .reg .u64 t; cvta.to.shared.u64 t, %1; cvt.u32.u64 %0, t; }" : "=r"(a) : "l"(p));
    return a;
}
__device__ __forceinline__ void cp16(uint32_t dst, const void* src) {
    ULL g;
    asm("cvta.to.global.u64 %0, %1;" : "=l"(g) : "l"(src));
    asm volatile("cp.async.cg.shared.global [%0], [%1], 16;" :: "r"(dst), "l"(g) : "memory");
}
#define CP_COMMIT() asm volatile("cp.async.commit_group;" ::: "memory")
#define CP_WAIT(n)  asm volatile("cp.async.wait_group %0;" :: "n"(n) : "memory")

__device__ __forceinline__ void ldsm_x4(uint32_t* r, uint32_t addr) {
    asm volatile("ldmatrix.sync.aligned.m8n8.x4.shared.b16 {%0,%1,%2,%3}, [%4];"
                 : "=r"(r[0]), "=r"(r[1]), "=r"(r[2]), "=r"(r[3]) : "r"(addr));
}
__device__ __forceinline__ void ldsm_x4t(uint32_t* r, uint32_t addr) {
    asm volatile("ldmatrix.sync.aligned.m8n8.x4.trans.shared.b16 {%0,%1,%2,%3}, [%4];"
                 : "=r"(r[0]), "=r"(r[1]), "=r"(r[2]), "=r"(r[3]) : "r"(addr));
}
__device__ __forceinline__ void mma_bf16(float* c, const uint32_t* a, const uint32_t* b) {
    asm volatile(
        "mma.sync.aligned.m16n8k16.row.col.f32.bf16.bf16.f32 "
        "{%0,%1,%2,%3}, {%4,%5,%6,%7}, {%8,%9}, {%0,%1,%2,%3};"
        : "+f"(c[0]), "+f"(c[1]), "+f"(c[2]), "+f"(c[3])
        : "r"(a[0]), "r"(a[1]), "r"(a[2]), "r"(a[3]), "r"(b[0]), "r"(b[1]));
}

// ================= prep kernels =================
__global__ void prep_w(const float* __restrict__ dw) {
    int idx = blockIdx.x * 256 + threadIdx.x;
    if (idx >= M_OUT * KDIM) return;
    int m = idx / KDIM, j = idx - m * KDIM;
    int g = j / (KKN * CG);
    int r = j - g * (KKN * CG);
    int k = r / CG;
    int c = r - k * CG;
    float v = dw[((size_t)m * C_IN + g * CG + c) * KKN + k];
    __nv_bfloat16 h = __float2bfloat16(v);
    g_A_hi[idx] = h;
    g_A_lo[idx] = __float2bfloat16(v - __bfloat162float(h));
}
__global__ void prep_w1(const float* __restrict__ offw) {
    int idx = blockIdx.x * 256 + threadIdx.x;
    if (idx >= M_PAD * KDIM) return;
    int m = idx / KDIM, j = idx - m * KDIM;
    float v = (m < M_OFF) ? offw[(size_t)m * KDIM + j] : 0.f;
    __nv_bfloat16 h = __float2bfloat16(v);
    g_A1_hi[idx] = h;
    g_A1_lo[idx] = __float2bfloat16(v - __bfloat162float(h));
}
__global__ void prep_x(const float* __restrict__ x) {
    size_t idx = (size_t)blockIdx.x * 256 + threadIdx.x;
    if (idx >= XPLANE) return;
    int wo = (int)(idx & 127);
    size_t rest = idx >> 7;
    int y = (int)(rest % H_IN);
    size_t nc = rest / H_IN;
    const float* row = x + (nc * H_IN + y) * W_IN;
    #pragma unroll
    for (int kx = 0; kx < 3; ++kx) {
        float v = row[wo + 2 * kx];
        __nv_bfloat16 h = __float2bfloat16(v);
        g_X_hi[kx * XPLANE + idx] = h;
        g_X_lo[kx * XPLANE + idx] = __float2bfloat16(v - __bfloat162float(h));
    }
}

// ================= GEMM1: offsets via HMMA (80m x 128n x 32k, 2-stage) =================
#define A1_PITCH 80
#define B1_PITCH 272
#define SA1 (M_PAD * A1_PITCH)           // 6400
#define SB1 (BK * B1_PITCH)              // 8704
#define OFF_A1H 0
#define OFF_A1L SA1
#define OFF_B1H (2 * SA1)
#define OFF_B1L (2 * SA1 + SB1)
#define BUF1 (2 * SA1 + 2 * SB1)         // 30208
#define SMEM1 (2 * BUF1)                 // 60416

__global__ void __launch_bounds__(256, 2)
gemm1_mma(const float* __restrict__ bias)
{
    extern __shared__ char smem[];
    const uint32_t sb = smem_u32(smem);

    const int tid = threadIdx.x;
    const int l   = tid & 31;
    const int wid = tid >> 5;
    const int n   = blockIdx.z;
    const int p0  = blockIdx.x * 128;
    const int ho0 = blockIdx.x;
    const int wn  = wid * 16;

    const int a_row = ((l >> 3) & 1) * 8 + (l & 7);
    const int a_kb  = (l >> 4) * 8;
    const int b_kr  = ((l >> 3) & 1) * 8 + (l & 7);
    const int b_nb  = (l >> 4) * 8;

    float acc[5][2][4];
    #pragma unroll
    for (int i = 0; i < 5; ++i)
        #pragma unroll
        for (int j = 0; j < 2; ++j)
            #pragma unroll
            for (int q = 0; q < 4; ++q) acc[i][j][q] = 0.f;

    auto load_tile = [&](int kt, int b) {
        uint32_t base = sb + b * BUF1;
        #pragma unroll
        for (int i = 0; i < 2; ++i) {
            int c = tid + i * 256;
            if (c < 320) {
                int r = c >> 2, j = c & 3;
                uint32_t dst = base + r * A1_PITCH + j * 16;
                cp16(dst + OFF_A1H, g_A1_hi + (size_t)r * KDIM + kt + j * 8);
                cp16(dst + OFF_A1L, g_A1_lo + (size_t)r * KDIM + kt + j * 8);
            }
        }
        #pragma unroll
        for (int i = 0; i < 2; ++i) {
            int c  = tid + i * 256;
            int r  = c >> 4;
            int ch = c & 15;
            int j  = kt + r;
            int ci = j / 9;
            int kk = j - ci * 9;
            int ky = kk / 3;
            int kx = kk - ky * 3;
            int y  = ho0 + 2 * ky;
            size_t src = (size_t)kx * XPLANE
                       + (((size_t)n * C_IN + ci) * H_IN + y) * 128 + ch * 8;
            uint32_t dst = base + r * B1_PITCH + ch * 16;
            cp16(dst + OFF_B1H, g_X_hi + src);
            cp16(dst + OFF_B1L, g_X_lo + src);
        }
        CP_COMMIT();
    };

    load_tile(0, 0);

    for (int t = 0; t < NT; ++t) {
        int b = t & 1;
        if (t + 1 < NT) {
            load_tile((t + 1) * BK, b ^ 1);
            CP_WAIT(1);
        } else {
            CP_WAIT(0);
        }
        __syncthreads();

        uint32_t base = sb + b * BUF1;
        #pragma unroll
        for (int k16 = 0; k16 < BK; k16 += 16) {
            uint32_t ah[5][4], bh[2][2], bl[2][2];
            #pragma unroll
            for (int mt = 0; mt < 5; ++mt)
                ldsm_x4(ah[mt], base + OFF_A1H + (mt * 16 + a_row) * A1_PITCH
                                + (k16 + a_kb) * 2);
            {
                uint32_t r[4];
                ldsm_x4t(r, base + OFF_B1H + (k16 + b_kr) * B1_PITCH
                            + (wn + b_nb) * 2);
                bh[0][0] = r[0]; bh[0][1] = r[1];
                bh[1][0] = r[2]; bh[1][1] = r[3];
            }
            #pragma unroll
            for (int mt = 0; mt < 5; ++mt)
                #pragma unroll
                for (int nt = 0; nt < 2; ++nt)
                    mma_bf16(acc[mt][nt], ah[mt], bh[nt]);
            {
                uint32_t r[4];
                ldsm_x4t(r, base + OFF_B1L + (k16 + b_kr) * B1_PITCH
                            + (wn + b_nb) * 2);
                bl[0][0] = r[0]; bl[0][1] = r[1];
                bl[1][0] = r[2]; bl[1][1] = r[3];
            }
            #pragma unroll
            for (int mt = 0; mt < 5; ++mt)
                #pragma unroll
                for (int nt = 0; nt < 2; ++nt)
                    mma_bf16(acc[mt][nt], ah[mt], bl[nt]);
            #pragma unroll
            for (int mt = 0; mt < 5; ++mt) {
                uint32_t al[4];
                ldsm_x4(al, base + OFF_A1L + (mt * 16 + a_row) * A1_PITCH
                            + (k16 + a_kb) * 2);
                #pragma unroll
                for (int nt = 0; nt < 2; ++nt)
                    mma_bf16(acc[mt][nt], al, bh[nt]);
            }
        }
        __syncthreads();
    }

    float* ob = g_off + (size_t)n * M_OFF * NP + p0 + wn;
    #pragma unroll
    for (int mt = 0; mt < 5; ++mt) {
        int row = mt * 16 + (l >> 2);
        float bv0 = bias[row];
        #pragma unroll
        for (int nt = 0; nt < 2; ++nt) {
            int col = nt * 8 + (l & 3) * 2;
            float* p = ob + (size_t)row * NP + col;
            *reinterpret_cast<float2*>(p) =
                make_float2(acc[mt][nt][0] + bv0, acc[mt][nt][1] + bv0);
        }
        if (mt < 4) {
            float bv1 = bias[row + 8];
            #pragma unroll
            for (int nt = 0; nt < 2; ++nt) {
                int col = nt * 8 + (l & 3) * 2;
                float* p = ob + (size_t)(row + 8) * NP + col;
                *reinterpret_cast<float2*>(p) =
                    make_float2(acc[mt][nt][2] + bv1, acc[mt][nt][3] + bv1);
            }
        }
    }
}

// ================= gather: bilinear sample, 2 pixels/thread (round-6 best) =================
__global__ void gather_sampled(const float* __restrict__ x) {
    int n  = blockIdx.z;
    int gk = blockIdx.y;
    int g  = gk / KKN, k = gk % KKN;
    int p  = (blockIdx.x * blockDim.x + threadIdx.x) * 2;
    int ho = p >> 7;
    int ky = k / 3, kx = k % 3;

    const float* offbase = g_off + ((size_t)n * M_OFF + g * 18 + k * 2) * NP + p;
    float2 dy = *reinterpret_cast<const float2*>(offbase);
    float2 dx = *reinterpret_cast<const float2*>(offbase + NP);

    float w00[2], w01[2], w10[2], w11[2];
    int i00[2], i01[2], i10[2], i11[2];
    #pragma unroll
    for (int s = 0; s < 2; ++s) {
        int wo = (p + s) & 127;
        float yf = (s ? dy.y : dy.x) + (float)(ky * 2 + ho);
        float xf = (s ? dx.y : dx.x) + (float)(kx * 2 + wo);
        float y0f = floorf(yf), x0f = floorf(xf);
        float ly = yf - y0f, lx = xf - x0f;
        int y0 = (int)y0f, x0 = (int)x0f;
        int y1 = y0 + 1,  x1 = x0 + 1;

        float a = (1.f - ly) * (1.f - lx);
        float b = (1.f - ly) * lx;
        float c = ly * (1.f - lx);
        float d = ly * lx;

        bool vy0 = (y0 >= 0) & (y0 < H_IN);
        bool vy1 = (y1 >= 0) & (y1 < H_IN);
        bool vx0 = (x0 >= 0) & (x0 < W_IN);
        bool vx1 = (x1 >= 0) & (x1 < W_IN);
        w00[s] = a * (float)(vy0 & vx0);
        w01[s] = b * (float)(vy0 & vx1);
        w10[s] = c * (float)(vy1 & vx0);
        w11[s] = d * (float)(vy1 & vx1);

        int cy0 = min(max(y0, 0), H_IN - 1);
        int cy1 = min(max(y1, 0), H_IN - 1);
        int cx0 = min(max(x0, 0), W_IN - 1);
        int cx1 = min(max(x1, 0), W_IN - 1);
        i00[s] = cy0 * W_IN + cx0;
        i01[s] = cy0 * W_IN + cx1;
        i10[s] = cy1 * W_IN + cx0;
        i11[s] = cy1 * W_IN + cx1;
    }

    const float* xb = x + ((size_t)n * C_IN + g * CG) * (H_IN * W_IN);
    size_t base = ((size_t)n * KDIM + (size_t)(g * KKN + k) * CG) * NP + p;
    __nv_bfloat16* hib = g_S_hi + base;
    __nv_bfloat16* lob = g_S_lo + base;

    #pragma unroll 2
    for (int c = 0; c < CG; ++c) {
        const float* xc = xb + c * (H_IN * W_IN);
        float v0 = w00[0] * __ldg(xc + i00[0]) + w01[0] * __ldg(xc + i01[0])
                 + w10[0] * __ldg(xc + i10[0]) + w11[0] * __ldg(xc + i11[0]);
        float v1 = w00[1] * __ldg(xc + i00[1]) + w01[1] * __ldg(xc + i01[1])
                 + w10[1] * __ldg(xc + i10[1]) + w11[1] * __ldg(xc + i11[1]);
        __nv_bfloat162 hp = __floats2bfloat162_rn(v0, v1);
        float r0 = v0 - __bfloat162float(hp.x);
        float r1 = v1 - __bfloat162float(hp.y);
        __nv_bfloat162 lp = __floats2bfloat162_rn(r0, r1);
        *reinterpret_cast<uint32_t*>(hib + (size_t)c * NP) = *reinterpret_cast<uint32_t*>(&hp);
        *reinterpret_cast<uint32_t*>(lob + (size_t)c * NP) = *reinterpret_cast<uint32_t*>(&lp);
    }
}

// ================= GEMM2: HMMA bf16, 3-term split, round-4 structure =================
#define A_PITCH 80
#define B_PITCH 272
#define SA_PLANE (128 * A_PITCH)
#define SB_PLANE (32 * B_PITCH)
#define OFF_AH 0
#define OFF_AL SA_PLANE
#define OFF_BH (2 * SA_PLANE)
#define OFF_BL (2 * SA_PLANE + SB_PLANE)
#define BUF_BYTES (2 * SA_PLANE + 2 * SB_PLANE)   // 37888
#define SMEM2_BYTES (2 * BUF_BYTES)               // 75776

__global__ void __launch_bounds__(256, 2)
gemm2_mma(float* __restrict__ out)
{
    extern __shared__ char smem[];
    const uint32_t sb = smem_u32(smem);

    const int tid = threadIdx.x;
    const int wid = tid >> 5;
    const int l   = tid & 31;

    const int my = blockIdx.x;
    const int bx = blockIdx.y;
    const int n  = blockIdx.z;

    const int wm = (wid & 1) * 64;
    const int wn = (wid >> 1) * 32;

    const __nv_bfloat16* Ah = g_A_hi + (size_t)my * 128 * KDIM;
    const __nv_bfloat16* Al = g_A_lo + (size_t)my * 128 * KDIM;
    const __nv_bfloat16* Sh = g_S_hi + (size_t)n * KDIM * NP + (size_t)bx * 128;
    const __nv_bfloat16* Sl = g_S_lo + (size_t)n * KDIM * NP + (size_t)bx * 128;

    const int a_row = ((l >> 3) & 1) * 8 + (l & 7);
    const int a_kb  = (l >> 4) * 8;
    const int b_kr  = ((l >> 3) & 1) * 8 + (l & 7);
    const int b_nb  = (l >> 4) * 8;

    float acc[4][4][4];
    #pragma unroll
    for (int i = 0; i < 4; ++i)
        #pragma unroll
        for (int j = 0; j < 4; ++j)
            #pragma unroll
            for (int q = 0; q < 4; ++q) acc[i][j][q] = 0.f;

    auto load_tile = [&](int kt, int b) {
        uint32_t base = sb + b * BUF_BYTES;
        #pragma unroll
        for (int i = 0; i < 2; ++i) {
            int c = tid + i * 256;
            int r = c >> 2, j = c & 3;
            uint32_t dst = base + r * A_PITCH + j * 16;
            cp16(dst + OFF_AH, Ah + (size_t)r * KDIM + kt + j * 8);
            cp16(dst + OFF_AL, Al + (size_t)r * KDIM + kt + j * 8);
        }
        #pragma unroll
        for (int i = 0; i < 2; ++i) {
            int c = tid + i * 256;
            int r = c >> 4, j = c & 15;
            uint32_t dst = base + r * B_PITCH + j * 16;
            cp16(dst + OFF_BH, Sh + (size_t)(kt + r) * NP + j * 8);
            cp16(dst + OFF_BL, Sl + (size_t)(kt + r) * NP + j * 8);
        }
        CP_COMMIT();
    };

    load_tile(0, 0);

    for (int t = 0; t < NT; ++t) {
        int b = t & 1;
        if (t + 1 < NT) {
            load_tile((t + 1) * BK, b ^ 1);
            CP_WAIT(1);
        } else {
            CP_WAIT(0);
        }
        __syncthreads();

        uint32_t base = sb + b * BUF_BYTES;
        #pragma unroll
        for (int k16 = 0; k16 < BK; k16 += 16) {
            #pragma unroll
            for (int pass = 0; pass < 3; ++pass) {
                uint32_t abase = base + ((pass == 2) ? OFF_AL : OFF_AH);
                uint32_t bbase = base + ((pass == 1) ? OFF_BL : OFF_BH);
                uint32_t afr[4][4];
                #pragma unroll
                for (int mt = 0; mt < 4; ++mt)
                    ldsm_x4(afr[mt],
                            abase + (wm + mt * 16 + a_row) * A_PITCH + (k16 + a_kb) * 2);
                uint32_t bfr[4][2];
                #pragma unroll
                for (int nt2 = 0; nt2 < 2; ++nt2) {
                    uint32_t r[4];
                    ldsm_x4t(r, bbase + (k16 + b_kr) * B_PITCH + (wn + nt2 * 16 + b_nb) * 2);
                    bfr[nt2 * 2][0]     = r[0];
                    bfr[nt2 * 2][1]     = r[1];
                    bfr[nt2 * 2 + 1][0] = r[2];
                    bfr[nt2 * 2 + 1][1] = r[3];
                }
                #pragma unroll
                for (int mt = 0; mt < 4; ++mt)
                    #pragma unroll
                    for (int nt = 0; nt < 4; ++nt)
                        mma_bf16(acc[mt][nt], afr[mt], bfr[nt]);
            }
        }
        __syncthreads();
    }

    float* ob = out + ((size_t)n * M_OUT + my * 128 + wm) * NP + (size_t)bx * 128 + wn;
    #pragma unroll
    for (int mt = 0; mt < 4; ++mt) {
        #pragma unroll
        for (int nt = 0; nt < 4; ++nt) {
            int row = mt * 16 + (l >> 2);
            int col = nt * 8 + (l & 3) * 2;
            float* p0 = ob + (size_t)row * NP + col;
            *reinterpret_cast<float2*>(p0) =
                make_float2(acc[mt][nt][0], acc[mt][nt][1]);
            *reinterpret_cast<float2*>(p0 + 8 * NP) =
                make_float2(acc[mt][nt][2], acc[mt][nt][3]);
        }
    }
}

// ---------------- launch ----------------
extern "C" void kernel_launch(void* const* d_in, const int* in_sizes, int n_in,
                              void* d_out, int out_size) {
    const float* x    = (const float*)d_in[0];
    const float* offw = (const float*)d_in[1];
    const float* offb = (const float*)d_in[2];
    const float* dw   = (const float*)d_in[3];
    float* out = (float*)d_out;

    cudaFuncSetAttribute(gemm1_mma, cudaFuncAttributeMaxDynamicSharedMemorySize, SMEM1);
    cudaFuncSetAttribute(gemm2_mma, cudaFuncAttributeMaxDynamicSharedMemorySize, SMEM2_BYTES);

    prep_w <<<(M_OUT * KDIM + 255) / 256, 256>>>(dw);
    prep_w1<<<(M_PAD * KDIM + 255) / 256, 256>>>(offw);
    prep_x <<<(int)((XPLANE + 255) / 256), 256>>>(x);
    // 1) offsets via tensor cores
    {
        dim3 grid(NP / 128, 1, N_B);
        gemm1_mma<<<grid, 256, SMEM1>>>(offb);
    }
    // 2) bilinear sampled matrix -> bf16 hi/lo planes (2 px/thread)
    {
        dim3 grid(NP / 512, GRP * KKN, N_B);
        gather_sampled<<<grid, 256>>>(x);
    }
    // 3) out = dw @ sampled
    {
        dim3 grid(2, NP / 128, N_B);
        gemm2_mma<<<grid, 256, SMEM2_BYTES>>>(out);
    }
}